// round 2
// baseline (speedup 1.0000x reference)
#include <cuda_runtime.h>
#include <math.h>

#define BB   32      // batch
#define LL   1024    // seq len
#define CC   34      // channels in x
#define DD   256     // model dim
#define EE   8       // experts
#define NQ   4       // patches that survive truncation (1024/256)
#define TT   (BB*NQ) // 128 token-patches
#define PRED 96

// ---------------- scratch (no allocations allowed) ----------------
__device__ float g_mean[BB];
__device__ float g_std[BB];
__device__ float g_xp[TT][DD];        // projected patches
__device__ float g_gates[TT][EE];     // router gates
__device__ float g_comb[TT][DD];      // gate-combined expert output
__device__ float g_Wt[EE][DD][DD];    // W_experts transposed: [e][d][h]

// ---------------- K1: transpose W_experts (e,h,d) -> (e,d,h) ----------------
__global__ void k_transpose(const float* __restrict__ W) {
    __shared__ float tile[32][33];
    int e  = blockIdx.z;
    int d0 = blockIdx.x * 32;
    int h0 = blockIdx.y * 32;
    int tx = threadIdx.x, ty = threadIdx.y;
    const float* We = W + e * DD * DD;
    #pragma unroll
    for (int j = 0; j < 32; j += 8)
        tile[ty + j][tx] = We[(h0 + ty + j) * DD + d0 + tx];
    __syncthreads();
    #pragma unroll
    for (int j = 0; j < 32; j += 8)
        g_Wt[e][d0 + ty + j][h0 + tx] = tile[tx][ty + j];
}

// ---------------- K2: per-row stats + patch proj + router softmax ----------------
__global__ __launch_bounds__(256) void k_stats(
    const float* __restrict__ x,
    const float* __restrict__ W_proj,  const float* __restrict__ b_proj,
    const float* __restrict__ W_router, const float* __restrict__ b_router)
{
    __shared__ float Wp_t[16][DD];   // W_proj transposed: [j][d]
    __shared__ float xc_s[64];
    __shared__ float xp_s[NQ][DD];
    __shared__ float red[2][8];
    __shared__ float logit_s[32];
    __shared__ float mean_sh, std_sh;

    int b = blockIdx.x, tid = threadIdx.x;

    // stage W_proj transposed (coalesced reads)
    #pragma unroll
    for (int i = 0; i < 16; i++) {
        int idx = tid + i * 256;            // idx = d*16 + j
        Wp_t[idx & 15][idx >> 4] = W_proj[idx];
    }

    // load this row's channel-2 values (strided gather)
    const float* xb = x + (long)b * LL * CC + 2;
    float v0 = xb[(tid      ) * CC];
    float v1 = xb[(tid + 256) * CC];
    float v2 = xb[(tid + 512) * CC];
    float v3 = xb[(tid + 768) * CC];
    float s1 = v0 + v1 + v2 + v3;
    float s2 = v0*v0 + v1*v1 + v2*v2 + v3*v3;
    #pragma unroll
    for (int o = 16; o; o >>= 1) {
        s1 += __shfl_down_sync(0xffffffffu, s1, o);
        s2 += __shfl_down_sync(0xffffffffu, s2, o);
    }
    if ((tid & 31) == 0) { red[0][tid >> 5] = s1; red[1][tid >> 5] = s2; }
    __syncthreads();
    if (tid == 0) {
        float a = 0.f, c = 0.f;
        #pragma unroll
        for (int i = 0; i < 8; i++) { a += red[0][i]; c += red[1][i]; }
        float m   = a / (float)LL;
        float var = c / (float)LL - m * m;
        float sd  = sqrtf(var + 1e-5f);
        mean_sh = m; std_sh = sd;
        g_mean[b] = m; g_std[b] = sd;
    }
    __syncthreads();
    float m = mean_sh, sd = std_sh;
    if (tid < 64) xc_s[tid] = (v0 - m) / sd;   // v0 holds l = tid
    __syncthreads();

    // xp[q][d], thread owns d = tid
    float bp = b_proj[tid];
    #pragma unroll
    for (int q = 0; q < NQ; q++) {
        float acc = bp;
        #pragma unroll
        for (int j = 0; j < 16; j++)
            acc += Wp_t[j][tid] * xc_s[q * 16 + j];
        xp_s[q][tid] = acc;
        g_xp[b * NQ + q][tid] = acc;
    }
    __syncthreads();

    // router logits: 32 threads, one (q,e) each
    if (tid < 32) {
        int q = tid >> 3, e = tid & 7;
        float acc = b_router[e];
        const float* wr = W_router + e * DD;
        #pragma unroll 8
        for (int d = 0; d < DD; d++) acc += wr[d] * xp_s[q][d];
        logit_s[tid] = acc;
    }
    __syncthreads();
    if (tid < NQ) {
        int q = tid;
        float mx = -1e30f;
        #pragma unroll
        for (int e = 0; e < 8; e++) mx = fmaxf(mx, logit_s[q * 8 + e]);
        float s = 0.f, ex[8];
        #pragma unroll
        for (int e = 0; e < 8; e++) { ex[e] = __expf(logit_s[q * 8 + e] - mx); s += ex[e]; }
        float inv = 1.f / s;
        #pragma unroll
        for (int e = 0; e < 8; e++) g_gates[b * NQ + q][e] = ex[e] * inv;
    }
}

// ---------------- K3: expert GEMM + gate-combine ----------------
// grid = 16 token-tiles (8 tokens) x 8 h-tiles (32 h) = 128 CTAs, 256 threads.
// thread = (e = tid>>5, hloc = tid&31), 8-token accumulators.
__global__ __launch_bounds__(256) void k_expert(const float* __restrict__ b_experts)
{
    __shared__ float xps[DD][8];       // [d][t], broadcast LDS.128 reads
    __shared__ float g_sh[8][EE];      // [t][e]
    __shared__ float sred[EE][32][8];  // [e][h][t]

    int bx = blockIdx.x;
    int tt = bx >> 3;          // token tile 0..15
    int ht = bx & 7;           // h tile 0..7
    int t0 = tt * 8, h0 = ht * 32;
    int tid = threadIdx.x;

    // stage xp transposed
    #pragma unroll
    for (int k = 0; k < 8; k++) {
        int idx = tid + k * 256;         // 2048 = 8 tokens * 256 d
        int t = idx >> 8, d = idx & 255;
        xps[d][t] = g_xp[t0 + t][d];
    }
    if (tid < 64) g_sh[tid >> 3][tid & 7] = g_gates[t0 + (tid >> 3)][tid & 7];
    __syncthreads();

    int e = tid >> 5;
    int hl = tid & 31;
    const float* wp = &g_Wt[e][0][h0 + hl];   // stride DD over d, coalesced over lanes
    float a0=0,a1=0,a2=0,a3=0,a4=0,a5=0,a6=0,a7=0;
    #pragma unroll 8
    for (int d = 0; d < DD; d++) {
        float w = wp[(long)d * DD];
        float4 xa = *(const float4*)&xps[d][0];
        float4 xb = *(const float4*)&xps[d][4];
        a0 += w * xa.x; a1 += w * xa.y; a2 += w * xa.z; a3 += w * xa.w;
        a4 += w * xb.x; a5 += w * xb.y; a6 += w * xb.z; a7 += w * xb.w;
    }
    float be = b_experts[e * DD + h0 + hl];
    float acc[8] = {a0,a1,a2,a3,a4,a5,a6,a7};
    #pragma unroll
    for (int t = 0; t < 8; t++)
        sred[e][hl][t] = g_sh[t][e] * (acc[t] + be);
    __syncthreads();

    // combine over e: thread = (t = tid>>5, h = tid&31); write coalesced in h
    int ot = tid >> 5, oh = tid & 31;
    float s = 0.f;
    #pragma unroll
    for (int e2 = 0; e2 < EE; e2++) s += sred[e2][oh][ot];
    g_comb[t0 + ot][h0 + oh] = s;
}

// ---------------- K4: head GEMV (mean term folded via row-sum) ----------------
__global__ __launch_bounds__(128) void k_head(
    const float* __restrict__ W_head, const float* __restrict__ b_head,
    float* __restrict__ out)
{
    __shared__ float fl[LL];
    int b = blockIdx.x, tid = threadIdx.x;
    for (int i = tid; i < LL; i += 128)
        fl[i] = g_comb[b * NQ + (i >> 8)][i & 255];
    __syncthreads();
    if (tid < PRED) {
        const float4* w4 = (const float4*)(W_head + tid * LL);
        float acc = 0.f, s = 0.f;
        #pragma unroll 4
        for (int i = 0; i < LL / 4; i++) {
            float4 w = w4[i];
            float4 f = *(const float4*)&fl[i * 4];
            s   += (w.x + w.y) + (w.z + w.w);
            acc += w.x * f.x + w.y * f.y + w.z * f.z + w.w * f.w;
        }
        out[b * PRED + tid] = b_head[tid] + g_mean[b] * s + g_std[b] * acc;
    }
}

// ---------------- launch ----------------
extern "C" void kernel_launch(void* const* d_in, const int* in_sizes, int n_in,
                              void* d_out, int out_size) {
    const float* x         = (const float*)d_in[0];
    const float* W_proj    = (const float*)d_in[4];
    const float* b_proj    = (const float*)d_in[5];
    const float* W_router  = (const float*)d_in[6];
    const float* b_router  = (const float*)d_in[7];
    const float* W_experts = (const float*)d_in[8];
    const float* b_experts = (const float*)d_in[9];
    const float* W_head    = (const float*)d_in[10];
    const float* b_head    = (const float*)d_in[11];
    float* out = (float*)d_out;

    k_transpose<<<dim3(8, 8, 8), dim3(32, 8)>>>(W_experts);
    k_stats<<<BB, 256>>>(x, W_proj, b_proj, W_router, b_router);
    k_expert<<<128, 256>>>(b_experts);
    k_head<<<BB, 128>>>(W_head, b_head, out);
}

// round 3
// speedup vs baseline: 1.5861x; 1.5861x over previous
#include <cuda_runtime.h>
#include <math.h>

#define BB   32      // batch
#define LL   1024    // seq len
#define CC   34      // channels in x
#define DD   256     // model dim
#define EE   8       // experts
#define NQ   4       // patches that survive truncation (1024/256)
#define TT   (BB*NQ) // 128 token-patches
#define PRED 96

// ---------------- scratch (no allocations allowed) ----------------
__device__ float g_mean[BB];
__device__ float g_std[BB];
__device__ float g_xp[TT][DD];        // projected patches
__device__ float g_gates[TT][EE];     // router gates
__device__ float g_comb[TT][DD];      // gate-combined expert output
__device__ float g_Wt[EE][DD][DD];    // W_experts transposed: [e][d][h]

// packed fp32x2 helpers
__device__ __forceinline__ unsigned long long pack2(float lo, float hi) {
    unsigned long long r;
    asm("mov.b64 %0, {%1, %2};" : "=l"(r) : "f"(lo), "f"(hi));
    return r;
}
__device__ __forceinline__ void unpack2(unsigned long long v, float& lo, float& hi) {
    asm("mov.b64 {%0, %1}, %2;" : "=f"(lo), "=f"(hi) : "l"(v));
}
__device__ __forceinline__ unsigned long long fma2(unsigned long long a,
                                                   unsigned long long b,
                                                   unsigned long long c) {
    unsigned long long r;
    asm("fma.rn.f32x2 %0, %1, %2, %3;" : "=l"(r) : "l"(a), "l"(b), "l"(c));
    return r;
}

// ---------------- K1: transpose W_experts (e,h,d) -> (e,d,h) ----------------
__global__ void k_transpose(const float* __restrict__ W) {
    __shared__ float tile[32][33];
    int e  = blockIdx.z;
    int d0 = blockIdx.x * 32;
    int h0 = blockIdx.y * 32;
    int tx = threadIdx.x, ty = threadIdx.y;
    const float* We = W + e * DD * DD;
    #pragma unroll
    for (int j = 0; j < 32; j += 8)
        tile[ty + j][tx] = We[(h0 + ty + j) * DD + d0 + tx];
    __syncthreads();
    #pragma unroll
    for (int j = 0; j < 32; j += 8)
        g_Wt[e][d0 + ty + j][h0 + tx] = tile[tx][ty + j];
}

// ---------------- K2: per-row stats + patch proj + router softmax ----------------
__global__ __launch_bounds__(256) void k_stats(
    const float* __restrict__ x,
    const float* __restrict__ W_proj,  const float* __restrict__ b_proj,
    const float* __restrict__ W_router, const float* __restrict__ b_router)
{
    __shared__ float Wp_t[16][DD + 1];  // W_proj transposed: [j][d], padded
    __shared__ float Wr[EE][DD];        // W_router staged (8 KB)
    __shared__ float xc_s[64];
    __shared__ float xp_s[NQ][DD];
    __shared__ float red[2][8];
    __shared__ float logit_s[32];
    __shared__ float mean_sh, std_sh;

    int b = blockIdx.x, tid = threadIdx.x;

    // stage W_proj transposed + W_router (coalesced reads)
    #pragma unroll
    for (int i = 0; i < 16; i++) {
        int idx = tid + i * 256;            // idx = d*16 + j
        Wp_t[idx & 15][idx >> 4] = W_proj[idx];
    }
    #pragma unroll
    for (int i = 0; i < 8; i++) {
        int idx = tid + i * 256;
        Wr[idx >> 8][idx & 255] = W_router[idx];
    }

    // load this row's channel-2 values (strided gather)
    const float* xb = x + (long)b * LL * CC + 2;
    float v0 = xb[(tid      ) * CC];
    float v1 = xb[(tid + 256) * CC];
    float v2 = xb[(tid + 512) * CC];
    float v3 = xb[(tid + 768) * CC];
    float s1 = v0 + v1 + v2 + v3;
    float s2 = v0*v0 + v1*v1 + v2*v2 + v3*v3;
    #pragma unroll
    for (int o = 16; o; o >>= 1) {
        s1 += __shfl_down_sync(0xffffffffu, s1, o);
        s2 += __shfl_down_sync(0xffffffffu, s2, o);
    }
    if ((tid & 31) == 0) { red[0][tid >> 5] = s1; red[1][tid >> 5] = s2; }
    __syncthreads();
    if (tid == 0) {
        float a = 0.f, c = 0.f;
        #pragma unroll
        for (int i = 0; i < 8; i++) { a += red[0][i]; c += red[1][i]; }
        float m   = a / (float)LL;
        float var = c / (float)LL - m * m;
        float sd  = sqrtf(var + 1e-5f);
        mean_sh = m; std_sh = sd;
        g_mean[b] = m; g_std[b] = sd;
    }
    __syncthreads();
    float m = mean_sh, sd = std_sh;
    if (tid < 64) xc_s[tid] = (v0 - m) / sd;   // v0 holds l = tid
    __syncthreads();

    // xp[q][d], thread owns d = tid
    float bp = b_proj[tid];
    #pragma unroll
    for (int q = 0; q < NQ; q++) {
        float acc = bp;
        #pragma unroll
        for (int j = 0; j < 16; j++)
            acc += Wp_t[j][tid] * xc_s[q * 16 + j];
        xp_s[q][tid] = acc;
        g_xp[b * NQ + q][tid] = acc;
    }
    __syncthreads();

    // router logits: all 256 threads. thread = (pair = tid>>3, k = tid&7)
    // pair = q*8 + e; each thread sums a 32-wide d-chunk with lane rotation
    {
        int pair = tid >> 3, k = tid & 7;
        int q = pair >> 3, e = pair & 7;
        float acc = 0.f;
        #pragma unroll
        for (int i = 0; i < 32; i++) {
            int ii = (i + tid) & 31;
            int d = k * 32 + ii;
            acc += Wr[e][d] * xp_s[q][d];
        }
        acc += __shfl_down_sync(0xffffffffu, acc, 4, 8);
        acc += __shfl_down_sync(0xffffffffu, acc, 2, 8);
        acc += __shfl_down_sync(0xffffffffu, acc, 1, 8);
        if (k == 0) logit_s[pair] = acc + b_router[e];
    }
    __syncthreads();
    if (tid < NQ) {
        int q = tid;
        float mx = -1e30f;
        #pragma unroll
        for (int e = 0; e < 8; e++) mx = fmaxf(mx, logit_s[q * 8 + e]);
        float s = 0.f, ex[8];
        #pragma unroll
        for (int e = 0; e < 8; e++) { ex[e] = __expf(logit_s[q * 8 + e] - mx); s += ex[e]; }
        float inv = 1.f / s;
        #pragma unroll
        for (int e = 0; e < 8; e++) g_gates[b * NQ + q][e] = ex[e] * inv;
    }
}

// ---------------- K3: expert GEMM + gate-combine (f32x2 packed) ----------------
// grid = 16 token-tiles (8 tokens) x 8 h-tiles (32 h) = 128 CTAs, 256 threads.
// thread = (e = tid>>5, hloc = tid&31); token-pairs in f32x2 accumulators.
__global__ __launch_bounds__(256) void k_expert(const float* __restrict__ b_experts)
{
    __shared__ float xps[DD][8];       // [d][t]; LDS.64 token-pairs
    __shared__ float g_sh[8][EE];      // [t][e]
    __shared__ float sred[EE][32][9];  // [e][h][t] padded -> conflict-free

    int bx = blockIdx.x;
    int tt = bx >> 3;          // token tile 0..15
    int ht = bx & 7;           // h tile 0..7
    int t0 = tt * 8, h0 = ht * 32;
    int tid = threadIdx.x;

    // stage xp transposed
    #pragma unroll
    for (int k = 0; k < 8; k++) {
        int idx = tid + k * 256;         // 2048 = 8 tokens * 256 d
        int t = idx >> 8, d = idx & 255;
        xps[d][t] = g_xp[t0 + t][d];
    }
    if (tid < 64) g_sh[tid >> 3][tid & 7] = g_gates[t0 + (tid >> 3)][tid & 7];
    __syncthreads();

    int e = tid >> 5;
    int hl = tid & 31;
    const float* wp = &g_Wt[e][0][h0 + hl];   // stride DD over d, coalesced over lanes
    unsigned long long acc0 = 0ull, acc1 = 0ull, acc2 = 0ull, acc3 = 0ull;
    #pragma unroll 8
    for (int d = 0; d < DD; d++) {
        float w = wp[(long)d * DD];
        unsigned long long w2 = pack2(w, w);
        const unsigned long long* xp2 = (const unsigned long long*)&xps[d][0];
        acc0 = fma2(w2, xp2[0], acc0);
        acc1 = fma2(w2, xp2[1], acc1);
        acc2 = fma2(w2, xp2[2], acc2);
        acc3 = fma2(w2, xp2[3], acc3);
    }
    float acc[8];
    unpack2(acc0, acc[0], acc[1]);
    unpack2(acc1, acc[2], acc[3]);
    unpack2(acc2, acc[4], acc[5]);
    unpack2(acc3, acc[6], acc[7]);

    float be = b_experts[e * DD + h0 + hl];
    #pragma unroll
    for (int t = 0; t < 8; t++)
        sred[e][hl][t] = g_sh[t][e] * (acc[t] + be);
    __syncthreads();

    // combine over e: thread = (t = tid>>5, h = tid&31); write coalesced in h
    int ot = tid >> 5, oh = tid & 31;
    float s = 0.f;
    #pragma unroll
    for (int e2 = 0; e2 < EE; e2++) s += sred[e2][oh][ot];
    g_comb[t0 + ot][h0 + oh] = s;
}

// ---------------- K4: head GEMV, warp-per-output, coalesced float4 ----------------
__global__ __launch_bounds__(256) void k_head(
    const float* __restrict__ W_head, const float* __restrict__ b_head,
    float* __restrict__ out)
{
    __shared__ float fl[LL];
    int b = blockIdx.x, tid = threadIdx.x;
    #pragma unroll
    for (int i = 0; i < 4; i++) {
        int idx = tid + i * 256;
        fl[idx] = g_comb[b * NQ + (idx >> 8)][idx & 255];
    }
    __syncthreads();

    int warp = tid >> 5, lane = tid & 31;
    const float4* W4  = (const float4*)W_head;  // [p][256] float4 per row
    const float4* fl4 = (const float4*)fl;
    float mb = g_mean[b], sb = g_std[b];

    #pragma unroll
    for (int j = 0; j < 12; j++) {
        int p = warp + j * 8;                   // 8 warps x 12 = 96 outputs
        float acc = 0.f, s = 0.f;
        #pragma unroll
        for (int i = 0; i < 8; i++) {
            float4 w = W4[p * 256 + i * 32 + lane];   // coalesced 512B
            float4 f = fl4[i * 32 + lane];
            acc += w.x * f.x + w.y * f.y + w.z * f.z + w.w * f.w;
            s   += (w.x + w.y) + (w.z + w.w);
        }
        #pragma unroll
        for (int o = 16; o; o >>= 1) {
            acc += __shfl_down_sync(0xffffffffu, acc, o);
            s   += __shfl_down_sync(0xffffffffu, s,   o);
        }
        if (lane == 0)
            out[b * PRED + p] = b_head[p] + mb * s + sb * acc;
    }
}

// ---------------- launch ----------------
extern "C" void kernel_launch(void* const* d_in, const int* in_sizes, int n_in,
                              void* d_out, int out_size) {
    const float* x         = (const float*)d_in[0];
    const float* W_proj    = (const float*)d_in[4];
    const float* b_proj    = (const float*)d_in[5];
    const float* W_router  = (const float*)d_in[6];
    const float* b_router  = (const float*)d_in[7];
    const float* W_experts = (const float*)d_in[8];
    const float* b_experts = (const float*)d_in[9];
    const float* W_head    = (const float*)d_in[10];
    const float* b_head    = (const float*)d_in[11];
    float* out = (float*)d_out;

    k_transpose<<<dim3(8, 8, 8), dim3(32, 8)>>>(W_experts);
    k_stats<<<BB, 256>>>(x, W_proj, b_proj, W_router, b_router);
    k_expert<<<128, 256>>>(b_experts);
    k_head<<<BB, 256>>>(W_head, b_head, out);
}

// round 6
// speedup vs baseline: 1.7941x; 1.1311x over previous
#include <cuda_runtime.h>
#include <math.h>

#define BB   32      // batch
#define LL   1024    // seq len
#define CC   34      // channels in x
#define DD   256     // model dim
#define EE   8       // experts
#define NQ   4       // patches that survive truncation (1024/256)
#define TT   (BB*NQ) // 128 token-patches
#define PRED 96

// ---------------- scratch (no allocations allowed) ----------------
__device__ float g_mean[BB];
__device__ float g_std[BB];
__device__ float g_ps1[BB][4];        // partial sums (quarters)
__device__ float g_ps2[BB][4];        // partial sum-squares
__device__ float g_xp[TT][DD];        // projected patches
__device__ float g_gates[TT][EE];     // router gates
__device__ float g_comb[TT][DD];      // gate-combined expert output
__device__ float g_Wt[EE][DD][DD];    // W_experts transposed: [e][d][h]

// packed fp32x2 helpers
__device__ __forceinline__ unsigned long long pack2(float lo, float hi) {
    unsigned long long r;
    asm("mov.b64 %0, {%1, %2};" : "=l"(r) : "f"(lo), "f"(hi));
    return r;
}
__device__ __forceinline__ void unpack2(unsigned long long v, float& lo, float& hi) {
    asm("mov.b64 {%0, %1}, %2;" : "=f"(lo), "=f"(hi) : "l"(v));
}
__device__ __forceinline__ unsigned long long fma2(unsigned long long a,
                                                   unsigned long long b,
                                                   unsigned long long c) {
    unsigned long long r;
    asm("fma.rn.f32x2 %0, %1, %2, %3;" : "=l"(r) : "l"(a), "l"(b), "l"(c));
    return r;
}

// ---------------- K1: transpose W_experts + x stats partials ----------------
// blocks [0,512): transpose tiles. blocks [512,640): per-(b,quarter) stats.
__global__ __launch_bounds__(256) void k_prep(const float* __restrict__ W,
                                              const float* __restrict__ x)
{
    __shared__ float tile[32][33];
    int bid = blockIdx.x, tid = threadIdx.x;

    if (bid < 512) {
        int e   = bid >> 6;
        int rem = bid & 63;
        int d0  = ((rem >> 3) & 7) * 32;
        int h0  = (rem & 7) * 32;
        int tx = tid & 31, ty = tid >> 5;
        const float* We = W + e * DD * DD;
        #pragma unroll
        for (int j = 0; j < 32; j += 8)
            tile[ty + j][tx] = We[(h0 + ty + j) * DD + d0 + tx];
        __syncthreads();
        #pragma unroll
        for (int j = 0; j < 32; j += 8)
            g_Wt[e][d0 + ty + j][h0 + tx] = tile[tx][ty + j];
    } else {
        int idx = bid - 512;
        int b = idx >> 2, q = idx & 3;
        int l = q * 256 + tid;
        float v = x[(long)b * LL * CC + (long)l * CC + 2];
        float s1 = v, s2 = v * v;
        #pragma unroll
        for (int o = 16; o; o >>= 1) {
            s1 += __shfl_down_sync(0xffffffffu, s1, o);
            s2 += __shfl_down_sync(0xffffffffu, s2, o);
        }
        __shared__ float red[8][2];
        if ((tid & 31) == 0) { red[tid >> 5][0] = s1; red[tid >> 5][1] = s2; }
        __syncthreads();
        if (tid == 0) {
            float a = 0.f, c = 0.f;
            #pragma unroll
            for (int i = 0; i < 8; i++) { a += red[i][0]; c += red[i][1]; }
            g_ps1[b][q] = a; g_ps2[b][q] = c;
        }
    }
}

// ---------------- K2: finalize stats + patch proj + router softmax ----------------
__global__ __launch_bounds__(256) void k_stats(
    const float* __restrict__ x,
    const float* __restrict__ W_proj,  const float* __restrict__ b_proj,
    const float* __restrict__ W_router, const float* __restrict__ b_router)
{
    __shared__ float Wp_t[16][DD + 1];  // W_proj transposed: [j][d], padded
    __shared__ float Wr[EE][DD];        // W_router staged (8 KB)
    __shared__ float xraw[64];
    __shared__ float xc_s[64];
    __shared__ float xp_s[NQ][DD];
    __shared__ float logit_s[32];
    __shared__ float mean_sh, std_sh;

    int b = blockIdx.x, tid = threadIdx.x;

    // stage W_proj transposed + W_router (coalesced reads)
    #pragma unroll
    for (int i = 0; i < 16; i++) {
        int idx = tid + i * 256;            // idx = d*16 + j
        Wp_t[idx & 15][idx >> 4] = W_proj[idx];
    }
    #pragma unroll
    for (int i = 0; i < 8; i++) {
        int idx = tid + i * 256;
        Wr[idx >> 8][idx & 255] = W_router[idx];
    }
    if (tid < 64)
        xraw[tid] = x[(long)b * LL * CC + (long)tid * CC + 2];
    if (tid == 0) {
        float a = g_ps1[b][0] + g_ps1[b][1] + g_ps1[b][2] + g_ps1[b][3];
        float c = g_ps2[b][0] + g_ps2[b][1] + g_ps2[b][2] + g_ps2[b][3];
        float m   = a / (float)LL;
        float var = c / (float)LL - m * m;
        float sd  = sqrtf(var + 1e-5f);
        mean_sh = m; std_sh = sd;
        g_mean[b] = m; g_std[b] = sd;
    }
    __syncthreads();
    float m = mean_sh, sd = std_sh;
    if (tid < 64) xc_s[tid] = (xraw[tid] - m) / sd;
    __syncthreads();

    // xp[q][d], thread owns d = tid
    float bp = b_proj[tid];
    #pragma unroll
    for (int q = 0; q < NQ; q++) {
        float acc = bp;
        #pragma unroll
        for (int j = 0; j < 16; j++)
            acc += Wp_t[j][tid] * xc_s[q * 16 + j];
        xp_s[q][tid] = acc;
        g_xp[b * NQ + q][tid] = acc;
    }
    __syncthreads();

    // router logits: all 256 threads. thread = (pair = tid>>3, k = tid&7)
    {
        int pair = tid >> 3, k = tid & 7;
        int q = pair >> 3, e = pair & 7;
        float acc = 0.f;
        #pragma unroll
        for (int i = 0; i < 32; i++) {
            int ii = (i + tid) & 31;
            int d = k * 32 + ii;
            acc += Wr[e][d] * xp_s[q][d];
        }
        acc += __shfl_down_sync(0xffffffffu, acc, 4, 8);
        acc += __shfl_down_sync(0xffffffffu, acc, 2, 8);
        acc += __shfl_down_sync(0xffffffffu, acc, 1, 8);
        if (k == 0) logit_s[pair] = acc + b_router[e];
    }
    __syncthreads();
    if (tid < NQ) {
        int q = tid;
        float mx = -1e30f;
        #pragma unroll
        for (int e = 0; e < 8; e++) mx = fmaxf(mx, logit_s[q * 8 + e]);
        float s = 0.f, ex[8];
        #pragma unroll
        for (int e = 0; e < 8; e++) { ex[e] = __expf(logit_s[q * 8 + e] - mx); s += ex[e]; }
        float inv = 1.f / s;
        #pragma unroll
        for (int e = 0; e < 8; e++) g_gates[b * NQ + q][e] = ex[e] * inv;
    }
}

// ---------------- K3: expert GEMM + gate-combine (f32x2 packed) ----------------
// grid = 16 token-tiles (8 tokens) x 8 h-tiles (32 h) = 128 CTAs, 256 threads.
__global__ __launch_bounds__(256) void k_expert(const float* __restrict__ b_experts)
{
    __shared__ float xps[DD][8];       // [d][t]; LDS.64 token-pairs
    __shared__ float g_sh[8][EE];      // [t][e]
    __shared__ float sred[EE][32][9];  // [e][h][t] padded -> conflict-free

    int bx = blockIdx.x;
    int tt = bx >> 3;          // token tile 0..15
    int ht = bx & 7;           // h tile 0..7
    int t0 = tt * 8, h0 = ht * 32;
    int tid = threadIdx.x;

    // stage xp transposed
    #pragma unroll
    for (int k = 0; k < 8; k++) {
        int idx = tid + k * 256;         // 2048 = 8 tokens * 256 d
        int t = idx >> 8, d = idx & 255;
        xps[d][t] = g_xp[t0 + t][d];
    }
    if (tid < 64) g_sh[tid >> 3][tid & 7] = g_gates[t0 + (tid >> 3)][tid & 7];
    __syncthreads();

    int e = tid >> 5;
    int hl = tid & 31;
    const float* wp = &g_Wt[e][0][h0 + hl];
    unsigned long long acc0 = 0ull, acc1 = 0ull, acc2 = 0ull, acc3 = 0ull;
    #pragma unroll 8
    for (int d = 0; d < DD; d++) {
        float w = wp[(long)d * DD];
        unsigned long long w2 = pack2(w, w);
        const unsigned long long* xp2 = (const unsigned long long*)&xps[d][0];
        acc0 = fma2(w2, xp2[0], acc0);
        acc1 = fma2(w2, xp2[1], acc1);
        acc2 = fma2(w2, xp2[2], acc2);
        acc3 = fma2(w2, xp2[3], acc3);
    }
    float acc[8];
    unpack2(acc0, acc[0], acc[1]);
    unpack2(acc1, acc[2], acc[3]);
    unpack2(acc2, acc[4], acc[5]);
    unpack2(acc3, acc[6], acc[7]);

    float be = b_experts[e * DD + h0 + hl];
    #pragma unroll
    for (int t = 0; t < 8; t++)
        sred[e][hl][t] = g_sh[t][e] * (acc[t] + be);
    __syncthreads();

    int ot = tid >> 5, oh = tid & 31;
    float s = 0.f;
    #pragma unroll
    for (int e2 = 0; e2 < EE; e2++) s += sred[e2][oh][ot];
    g_comb[t0 + ot][h0 + oh] = s;
}

// ---------------- K4: head GEMV, grid = 12 p-tiles x 16 b-pairs ----------------
// warp = one p; computes out[b0][p] and out[b1][p] sharing W loads.
__global__ __launch_bounds__(256) void k_head(
    const float* __restrict__ W_head, const float* __restrict__ b_head,
    float* __restrict__ out)
{
    __shared__ float fl[2][LL];
    int pt = blockIdx.x;          // 0..11
    int bp = blockIdx.y;          // 0..15
    int b0 = bp * 2, b1 = b0 + 1;
    int tid = threadIdx.x;

    #pragma unroll
    for (int i = 0; i < 8; i++) {
        int idx = tid + i * 256;               // 2048 = 2 b * 1024
        int bb = idx >> 10, l = idx & 1023;
        fl[bb][idx & 1023] = g_comb[(b0 + bb) * NQ + (l >> 8)][l & 255];
    }
    __syncthreads();

    int warp = tid >> 5, lane = tid & 31;
    int p = pt * 8 + warp;
    const float4* W4  = (const float4*)(W_head + p * LL);
    const float4* f04 = (const float4*)fl[0];
    const float4* f14 = (const float4*)fl[1];

    float a0 = 0.f, a1 = 0.f, s = 0.f;
    #pragma unroll
    for (int i = 0; i < 8; i++) {
        float4 w  = W4[i * 32 + lane];          // coalesced 512B
        float4 f0 = f04[i * 32 + lane];
        float4 f1 = f14[i * 32 + lane];
        a0 += w.x * f0.x + w.y * f0.y + w.z * f0.z + w.w * f0.w;
        a1 += w.x * f1.x + w.y * f1.y + w.z * f1.z + w.w * f1.w;
        s  += (w.x + w.y) + (w.z + w.w);
    }
    #pragma unroll
    for (int o = 16; o; o >>= 1) {
        a0 += __shfl_down_sync(0xffffffffu, a0, o);
        a1 += __shfl_down_sync(0xffffffffu, a1, o);
        s  += __shfl_down_sync(0xffffffffu, s,  o);
    }
    if (lane == 0) {
        float bh = b_head[p];
        out[b0 * PRED + p] = bh + g_mean[b0] * s + g_std[b0] * a0;
        out[b1 * PRED + p] = bh + g_mean[b1] * s + g_std[b1] * a1;
    }
}

// ---------------- launch ----------------
extern "C" void kernel_launch(void* const* d_in, const int* in_sizes, int n_in,
                              void* d_out, int out_size) {
    const float* x         = (const float*)d_in[0];
    const float* W_proj    = (const float*)d_in[4];
    const float* b_proj    = (const float*)d_in[5];
    const float* W_router  = (const float*)d_in[6];
    const float* b_router  = (const float*)d_in[7];
    const float* W_experts = (const float*)d_in[8];
    const float* b_experts = (const float*)d_in[9];
    const float* W_head    = (const float*)d_in[10];
    const float* b_head    = (const float*)d_in[11];
    float* out = (float*)d_out;

    k_prep<<<640, 256>>>(W_experts, x);
    k_stats<<<BB, 256>>>(x, W_proj, b_proj, W_router, b_router);
    k_expert<<<128, 256>>>(b_experts);
    k_head<<<dim3(12, 16), 256>>>(W_head, b_head, out);
}

// round 8
// speedup vs baseline: 2.0456x; 1.1402x over previous
#include <cuda_runtime.h>
#include <math.h>

#define BB   32      // batch
#define LL   1024    // seq len
#define CC   34      // channels in x
#define DD   256     // model dim
#define EE   8       // experts
#define NQ   4       // patches that survive truncation (1024/256)
#define TT   (BB*NQ) // 128 token-patches
#define PRED 96

// ---------------- scratch (no allocations allowed) ----------------
__device__ float g_mean[BB];
__device__ float g_std[BB];
__device__ float g_xp[TT][DD];        // projected patches
__device__ float g_gates[TT][EE];     // router gates
__device__ float g_comb[TT][DD];      // gate-combined expert output
__device__ float g_Wt[EE][DD][DD];    // W_experts transposed: [e][d][h]

// packed fp32x2 helpers
__device__ __forceinline__ unsigned long long pack2(float lo, float hi) {
    unsigned long long r;
    asm("mov.b64 %0, {%1, %2};" : "=l"(r) : "f"(lo), "f"(hi));
    return r;
}
__device__ __forceinline__ void unpack2(unsigned long long v, float& lo, float& hi) {
    asm("mov.b64 {%0, %1}, %2;" : "=f"(lo), "=f"(hi) : "l"(v));
}
__device__ __forceinline__ unsigned long long fma2(unsigned long long a,
                                                   unsigned long long b,
                                                   unsigned long long c) {
    unsigned long long r;
    asm("fma.rn.f32x2 %0, %1, %2, %3;" : "=l"(r) : "l"(a), "l"(b), "l"(c));
    return r;
}

// ---------------- K1: fused (stats+proj+router) || transpose ----------------
// blocks [0,32): full per-b stats + patch proj + router softmax (critical path,
//                scheduled first). blocks [32,544): W_experts transpose tiles.
union SmemU {
    struct { float tile[32][33]; } tr;
    struct {
        float Wp_t[16][DD + 1];
        float Wr[EE][DD];
        float xc[64];
        float xp[NQ][DD];
        float red[2][8];
        float logit[32];
        float mean, std;
    } st;
};

__global__ __launch_bounds__(256) void k_prep(const float* __restrict__ W,
                                              const float* __restrict__ x,
                                              const float* __restrict__ W_proj,
                                              const float* __restrict__ b_proj,
                                              const float* __restrict__ W_router,
                                              const float* __restrict__ b_router)
{
    __shared__ SmemU sm;
    int bid = blockIdx.x, tid = threadIdx.x;

    if (bid >= 32) {
        // ---- transpose path ----
        int id  = bid - 32;              // 0..511
        int e   = id >> 6;
        int rem = id & 63;
        int d0  = ((rem >> 3) & 7) * 32;
        int h0  = (rem & 7) * 32;
        int tx = tid & 31, ty = tid >> 5;
        const float* We = W + e * DD * DD;
        #pragma unroll
        for (int j = 0; j < 32; j += 8)
            sm.tr.tile[ty + j][tx] = We[(h0 + ty + j) * DD + d0 + tx];
        __syncthreads();
        #pragma unroll
        for (int j = 0; j < 32; j += 8)
            g_Wt[e][d0 + ty + j][h0 + tx] = sm.tr.tile[tx][ty + j];
        return;
    }

    // ---- stats + proj + router path ----
    int b = bid;

    // stage W_proj transposed + W_router (coalesced reads)
    #pragma unroll
    for (int i = 0; i < 16; i++) {
        int idx = tid + i * 256;            // idx = d*16 + j
        sm.st.Wp_t[idx & 15][idx >> 4] = W_proj[idx];
    }
    #pragma unroll
    for (int i = 0; i < 8; i++) {
        int idx = tid + i * 256;
        sm.st.Wr[idx >> 8][idx & 255] = W_router[idx];
    }

    // full gather of channel-2 row (strided)
    const float* xb = x + (long)b * LL * CC + 2;
    float v0 = xb[(tid      ) * CC];
    float v1 = xb[(tid + 256) * CC];
    float v2 = xb[(tid + 512) * CC];
    float v3 = xb[(tid + 768) * CC];
    float s1 = v0 + v1 + v2 + v3;
    float s2 = v0*v0 + v1*v1 + v2*v2 + v3*v3;
    #pragma unroll
    for (int o = 16; o; o >>= 1) {
        s1 += __shfl_down_sync(0xffffffffu, s1, o);
        s2 += __shfl_down_sync(0xffffffffu, s2, o);
    }
    if ((tid & 31) == 0) { sm.st.red[0][tid >> 5] = s1; sm.st.red[1][tid >> 5] = s2; }
    __syncthreads();
    if (tid == 0) {
        float a = 0.f, c = 0.f;
        #pragma unroll
        for (int i = 0; i < 8; i++) { a += sm.st.red[0][i]; c += sm.st.red[1][i]; }
        float m   = a / (float)LL;
        float var = c / (float)LL - m * m;
        float sd  = sqrtf(var + 1e-5f);
        sm.st.mean = m; sm.st.std = sd;
        g_mean[b] = m; g_std[b] = sd;
    }
    __syncthreads();
    float m = sm.st.mean, sd = sm.st.std;
    if (tid < 64) sm.st.xc[tid] = (v0 - m) / sd;   // v0 holds l = tid
    __syncthreads();

    // xp[q][d], thread owns d = tid
    float bp = b_proj[tid];
    #pragma unroll
    for (int q = 0; q < NQ; q++) {
        float acc = bp;
        #pragma unroll
        for (int j = 0; j < 16; j++)
            acc += sm.st.Wp_t[j][tid] * sm.st.xc[q * 16 + j];
        sm.st.xp[q][tid] = acc;
        g_xp[b * NQ + q][tid] = acc;
    }
    __syncthreads();

    // router logits: all 256 threads. thread = (pair = tid>>3, k = tid&7)
    {
        int pair = tid >> 3, k = tid & 7;
        int q = pair >> 3, e = pair & 7;
        float acc = 0.f;
        #pragma unroll
        for (int i = 0; i < 32; i++) {
            int ii = (i + tid) & 31;
            int d = k * 32 + ii;
            acc += sm.st.Wr[e][d] * sm.st.xp[q][d];
        }
        acc += __shfl_down_sync(0xffffffffu, acc, 4, 8);
        acc += __shfl_down_sync(0xffffffffu, acc, 2, 8);
        acc += __shfl_down_sync(0xffffffffu, acc, 1, 8);
        if (k == 0) sm.st.logit[pair] = acc + b_router[e];
    }
    __syncthreads();
    if (tid < NQ) {
        int q = tid;
        float mx = -1e30f;
        #pragma unroll
        for (int e = 0; e < 8; e++) mx = fmaxf(mx, sm.st.logit[q * 8 + e]);
        float s = 0.f, ex[8];
        #pragma unroll
        for (int e = 0; e < 8; e++) { ex[e] = __expf(sm.st.logit[q * 8 + e] - mx); s += ex[e]; }
        float inv = 1.f / s;
        #pragma unroll
        for (int e = 0; e < 8; e++) g_gates[b * NQ + q][e] = ex[e] * inv;
    }
}

// ---------------- K2: expert GEMM + gate-combine (f32x2, 16 tok/CTA) ----------------
// grid = 8 token-tiles (16 tokens) x 16 h-tiles (16 h) = 128 CTAs, 128 threads.
// thread = (e = tid>>4, hl = tid&15); 16 tokens = 8 f32x2 accumulators.
__global__ __launch_bounds__(128) void k_expert(const float* __restrict__ b_experts)
{
    __shared__ float xps[DD][18];      // [d][t] (stride 18: 8B-aligned, low conflict)
    __shared__ float g_sh[16][EE];     // [t][e]
    __shared__ float sred[EE][16][17]; // [e][h][t] (conflict-free)

    int bx = blockIdx.x;
    int tt = bx >> 4;          // token tile 0..7
    int ht = bx & 15;          // h tile 0..15
    int t0 = tt * 16, h0 = ht * 16;
    int tid = threadIdx.x;

    // stage xp transposed: 16 tokens x 256 d
    #pragma unroll
    for (int k = 0; k < 32; k++) {
        int idx = tid + k * 128;         // 4096
        int t = idx >> 8, d = idx & 255;
        xps[d][t] = g_xp[t0 + t][d];
    }
    g_sh[tid >> 3][tid & 7] = g_gates[t0 + (tid >> 3)][tid & 7];
    __syncthreads();

    int e = tid >> 4;
    int hl = tid & 15;
    const float* wp = &g_Wt[e][0][h0 + hl];
    unsigned long long a0=0,a1=0,a2=0,a3=0,a4=0,a5=0,a6=0,a7=0;
    #pragma unroll 8
    for (int d = 0; d < DD; d++) {
        float w = wp[(long)d * DD];
        unsigned long long w2 = pack2(w, w);
        const unsigned long long* xp2 = (const unsigned long long*)&xps[d][0];
        a0 = fma2(w2, xp2[0], a0);
        a1 = fma2(w2, xp2[1], a1);
        a2 = fma2(w2, xp2[2], a2);
        a3 = fma2(w2, xp2[3], a3);
        a4 = fma2(w2, xp2[4], a4);
        a5 = fma2(w2, xp2[5], a5);
        a6 = fma2(w2, xp2[6], a6);
        a7 = fma2(w2, xp2[7], a7);
    }
    float acc[16];
    unpack2(a0, acc[0],  acc[1]);
    unpack2(a1, acc[2],  acc[3]);
    unpack2(a2, acc[4],  acc[5]);
    unpack2(a3, acc[6],  acc[7]);
    unpack2(a4, acc[8],  acc[9]);
    unpack2(a5, acc[10], acc[11]);
    unpack2(a6, acc[12], acc[13]);
    unpack2(a7, acc[14], acc[15]);

    float be = b_experts[e * DD + h0 + hl];
    #pragma unroll
    for (int t = 0; t < 16; t++)
        sred[e][hl][t] = g_sh[t][e] * (acc[t] + be);
    __syncthreads();

    // combine over e: thread = (tq = tid>>4, h = tid&15); two t values each
    int tq = tid >> 4, oh = tid & 15;
    #pragma unroll
    for (int half = 0; half < 2; half++) {
        int t = tq + half * 8;
        float s = 0.f;
        #pragma unroll
        for (int e2 = 0; e2 < EE; e2++) s += sred[e2][oh][t];
        g_comb[t0 + t][h0 + oh] = s;
    }
}

// ---------------- K3: head GEMV, grid = 12 p-tiles x 8 b-quads ----------------
// warp = one p; computes out[b0..b0+3][p] sharing W loads (4x reuse, 4x ILP).
__global__ __launch_bounds__(256) void k_head(
    const float* __restrict__ W_head, const float* __restrict__ b_head,
    float* __restrict__ out)
{
    __shared__ float fl[4][LL];
    int pt = blockIdx.x;          // 0..11
    int bq = blockIdx.y;          // 0..7
    int b0 = bq * 4;
    int tid = threadIdx.x;

    #pragma unroll
    for (int i = 0; i < 16; i++) {
        int idx = tid + i * 256;               // 4096 = 4 b * 1024
        int bb = idx >> 10, l = idx & 1023;
        fl[bb][l] = g_comb[(b0 + bb) * NQ + (l >> 8)][l & 255];
    }
    __syncthreads();

    int warp = tid >> 5, lane = tid & 31;
    int p = pt * 8 + warp;
    const float4* W4 = (const float4*)(W_head + p * LL);
    const float4* f0 = (const float4*)fl[0];
    const float4* f1 = (const float4*)fl[1];
    const float4* f2 = (const float4*)fl[2];
    const float4* f3 = (const float4*)fl[3];

    float a0 = 0.f, a1 = 0.f, a2 = 0.f, a3 = 0.f, s = 0.f;
    #pragma unroll
    for (int i = 0; i < 8; i++) {
        int off = i * 32 + lane;
        float4 w = W4[off];                    // coalesced 512B
        float4 x0 = f0[off], x1 = f1[off], x2 = f2[off], x3 = f3[off];
        a0 += w.x * x0.x + w.y * x0.y + w.z * x0.z + w.w * x0.w;
        a1 += w.x * x1.x + w.y * x1.y + w.z * x1.z + w.w * x1.w;
        a2 += w.x * x2.x + w.y * x2.y + w.z * x2.z + w.w * x2.w;
        a3 += w.x * x3.x + w.y * x3.y + w.z * x3.z + w.w * x3.w;
        s  += (w.x + w.y) + (w.z + w.w);
    }
    #pragma unroll
    for (int o = 16; o; o >>= 1) {
        a0 += __shfl_down_sync(0xffffffffu, a0, o);
        a1 += __shfl_down_sync(0xffffffffu, a1, o);
        a2 += __shfl_down_sync(0xffffffffu, a2, o);
        a3 += __shfl_down_sync(0xffffffffu, a3, o);
        s  += __shfl_down_sync(0xffffffffu, s,  o);
    }
    if (lane == 0) {
        float bh = b_head[p];
        out[(b0 + 0) * PRED + p] = bh + g_mean[b0 + 0] * s + g_std[b0 + 0] * a0;
        out[(b0 + 1) * PRED + p] = bh + g_mean[b0 + 1] * s + g_std[b0 + 1] * a1;
        out[(b0 + 2) * PRED + p] = bh + g_mean[b0 + 2] * s + g_std[b0 + 2] * a2;
        out[(b0 + 3) * PRED + p] = bh + g_mean[b0 + 3] * s + g_std[b0 + 3] * a3;
    }
}

// ---------------- launch ----------------
extern "C" void kernel_launch(void* const* d_in, const int* in_sizes, int n_in,
                              void* d_out, int out_size) {
    const float* x         = (const float*)d_in[0];
    const float* W_proj    = (const float*)d_in[4];
    const float* b_proj    = (const float*)d_in[5];
    const float* W_router  = (const float*)d_in[6];
    const float* b_router  = (const float*)d_in[7];
    const float* W_experts = (const float*)d_in[8];
    const float* b_experts = (const float*)d_in[9];
    const float* W_head    = (const float*)d_in[10];
    const float* b_head    = (const float*)d_in[11];
    float* out = (float*)d_out;

    k_prep<<<544, 256>>>(W_experts, x, W_proj, b_proj, W_router, b_router);
    k_expert<<<128, 128>>>(b_experts);
    k_head<<<dim3(12, 8), 256>>>(W_head, b_head, out);
}